// round 17
// baseline (speedup 1.0000x reference)
#include <cuda_runtime.h>

// ---------------------------------------------------------------------------
// Fused BasicBlockA, round 17 = R16 (125.4us) + depth-2 latent pipeline.
//  - 4 h buffers; between barriers: s1(l+2),s1(l+3) || s2(l),s2(l+1)
//    -> 4 independent conv chains per region, 8 barriers total (was 16).
//  - s1 latent-pair shares its 12 odd-parity x loads (latent-invariant).
//  - parity-split tiles, NT=160, weights scheme, launch_bounds(160,4): as R16.
// ---------------------------------------------------------------------------

#define L_DIM 16
#define TX 32
#define TY 16
#define NT 160
#define XQ 10        // xsE pair q = x rel rows (2q-4, 2q-3)
#define XO 9         // xsO pair t = x rel rows (2t-3, 2t-2)
#define PS 9         // h pair p = h rel rows (2p-2, 2p-1)
#define XCOLS 37
#define ACOLS 19
#define HACOLS 18
#define NS1 (PS * 17)  // 153

typedef unsigned long long u64;

struct WB2 {
    float w[2][L_DIM][3][16];
    u64   b[L_DIM][3];
};
__device__ WB2 g_wb;

__device__ __forceinline__ float softplus_f(float v) {
    return fmaxf(v, 0.f) + log1pf(expf(-fabsf(v)));
}
__device__ __forceinline__ u64 pack2(float lo, float hi) {
    u64 r; asm("mov.b64 %0, {%1, %2};" : "=l"(r) : "f"(lo), "f"(hi)); return r;
}
__device__ __forceinline__ void unpack2(u64 v, float& lo, float& hi) {
    asm("mov.b64 {%0, %1}, %2;" : "=f"(lo), "=f"(hi) : "l"(v));
}
__device__ __forceinline__ u64 fma2(u64 a, u64 b, u64 c) {
    u64 d; asm("fma.rn.f32x2 %0, %1, %2, %3;" : "=l"(d) : "l"(a), "l"(b), "l"(c)); return d;
}
__device__ __forceinline__ u64 dup2(float f) { return pack2(f, f); }
__device__ __forceinline__ u64 cmb(u64 A, u64 B) {   // (A.hi, B.lo)
    float al, ah, bl, bh;
    unpack2(A, al, ah); unpack2(B, bl, bh);
    return pack2(ah, bl);
}

__device__ __host__ __forceinline__ constexpr int goff(int j, int i) {
    constexpr int t[3][3] = {{0, 5, 10}, {0, 4, 9}, {0, 4, 8}};
    return t[j][i];
}

__global__ void prep_kernel(const float* __restrict__ w1, const float* __restrict__ c1,
                            const float* __restrict__ bias1,
                            const float* __restrict__ w2, const float* __restrict__ c2) {
    int t = threadIdx.x;
    if (t >= 2 * L_DIM) return;
    int stage = t >> 4;
    int l = t & 15;
    const float* W = stage ? w2 : w1;
    const float* C = stage ? c2 : c1;
    for (int j = 0; j < 3; j++) {
        float* dst = g_wb.w[stage][l][j];
        for (int k = 0; k < 16; k++) dst[k] = 0.f;
        for (int i = 0; i < 3; i++) {
            int base = ((l * 3 + i) * 3 + j) * 9;
            int k = goff(j, i);
            dst[k + 0] = W[base + 0];
            dst[k + 1] = W[base + 1];
            dst[k + 2] = W[base + 2];
            dst[k + 3] = W[base + 3];
            if (j <= i)
                dst[k + 4] = (j == i) ? softplus_f(C[base + 4]) : W[base + 4];
        }
    }
    if (stage == 0)
        for (int i = 0; i < 3; i++)
            g_wb.b[l][i] = pack2(bias1[l * 3 + i], bias1[l * 3 + i]);
}

template <int J>
__device__ __forceinline__ void conv_j(const float (&wf)[16], u64 a[3],
                                       u64 s0, u64 s1, u64 s2, u64 s3, u64 s4) {
#pragma unroll
    for (int i = 0; i < 3; i++) {
        const int k = goff(J, i);
        a[i] = fma2(dup2(wf[k + 0]), s0, a[i]);
        a[i] = fma2(dup2(wf[k + 1]), s1, a[i]);
        a[i] = fma2(dup2(wf[k + 2]), s2, a[i]);
        a[i] = fma2(dup2(wf[k + 3]), s3, a[i]);
        if (J <= i) a[i] = fma2(dup2(wf[k + 4]), s4, a[i]);
    }
}

__device__ __forceinline__ float elu_f(float v) {
    return (v > 0.f) ? v : (__expf(v) - 1.f);
}

__global__ __launch_bounds__(NT, 4)
void fused_kernel(const float* __restrict__ x, const float* __restrict__ res,
                  float* __restrict__ out) {
    __shared__ alignas(16) WB2 swb;
    __shared__ u64 xsE[3][XQ][XCOLS];
    __shared__ u64 xsOA[3][XO][ACOLS];
    __shared__ u64 xsOB[3][XO][ACOLS];
    __shared__ u64 hsA[4][3][PS][HACOLS];
    __shared__ u64 hsB[4][3][PS][HACOLS];

    const int tid = threadIdx.x;
    const int b   = blockIdx.z;
    const int gy0 = blockIdx.y * TY;
    const int gx0 = blockIdx.x * TX;

    // ---- weights/bias into SMEM ----
    {
        const u64* src = (const u64*)&g_wb;
        u64* dst = (u64*)&swb;
        const int n = sizeof(WB2) / 8;
        for (int q = tid; q < n; q += NT) dst[q] = src[q];
    }

    // ---- x tile, even pair layout ----
    const float* xb = x + (size_t)b * 3 * 128 * 128;
    for (int q = tid; q < 3 * XQ * XCOLS; q += NT) {
        int j  = q / (XQ * XCOLS);
        int r  = (q / XCOLS) % XQ;
        int cc = q % XCOLS;
        int gy = gy0 + 2 * r - 4;
        int gx = gx0 + cc - 2;
        float lo = 0.f, hi = 0.f;
        if ((unsigned)gx < 128u) {
            const float* col = xb + (size_t)j * 128 * 128 + gx;
            if ((unsigned)gy < 128u)       lo = col[(size_t)gy * 128];
            if ((unsigned)(gy + 1) < 128u) hi = col[(size_t)(gy + 1) * 128];
        }
        xsE[j][r][cc] = pack2(lo, hi);
    }
    __syncthreads();

    // ---- odd-row-parity x copy, split by column parity ----
    for (int q = tid; q < 3 * XO * ACOLS; q += NT) {
        int j = q / (XO * ACOLS);
        int t = (q / ACOLS) % XO;
        int k = q % ACOLS;
        xsOA[j][t][k] = cmb(xsE[j][t][2 * k], xsE[j][t + 1][2 * k]);
        if (k < ACOLS - 1)
            xsOB[j][t][k] = cmb(xsE[j][t][2 * k + 1], xsE[j][t + 1][2 * k + 1]);
    }

    // ---- stage-1 decode (latent-invariant) ----
    const bool sact = (tid < NS1);
    const int ps0 = sact ? tid / 17 : 0;
    const int pc0 = sact ? tid % 17 : 0;
    const int hcA = 2 * pc0;
    const bool cokA = ((unsigned)(gx0 + hcA - 1) < 128u);
    const bool cokB = ((unsigned)(gx0 + hcA) < 128u);
    const bool rlo  = ((unsigned)(gy0 + 2 * ps0 - 2) < 128u);
    const bool rhi  = ((unsigned)(gy0 + 2 * ps0 - 1) < 128u);

    // ---- stage-2 decode ----
    const bool s2act = (tid < 128);
    const int tcx = tid & 15;
    const int tpy = tid >> 4;

    __syncthreads();   // xsOA/xsOB ready

    // hoist stage-1 even-row words (latent-invariant)
    u64 Mh[3][3];
#pragma unroll
    for (int j = 0; j < 3; j++) {
        const u64* m = &xsE[j][ps0 + 1][hcA];
        Mh[j][0] = m[0]; Mh[j][1] = m[1]; Mh[j][2] = m[2];
    }

    // hoisted base pointers
    const u64* xoA0 = &xsOA[0][ps0][pc0];
    const u64* xoB0 = &xsOB[0][ps0][pc0];
    u64* hwA[4] = { &hsA[0][0][ps0][pc0], &hsA[1][0][ps0][pc0],
                    &hsA[2][0][ps0][pc0], &hsA[3][0][ps0][pc0] };
    u64* hwB[4] = { &hsB[0][0][ps0][pc0], &hsB[1][0][ps0][pc0],
                    &hsB[2][0][ps0][pc0], &hsB[3][0][ps0][pc0] };
    const u64* rA[4] = { &hsA[0][0][tpy][tcx], &hsA[1][0][tpy][tcx],
                         &hsA[2][0][tpy][tcx], &hsA[3][0][tpy][tcx] };
    const u64* rB[4] = { &hsB[0][0][tpy][tcx], &hsB[1][0][tpy][tcx],
                         &hsB[2][0][tpy][tcx], &hsB[3][0][tpy][tcx] };

    u64 accA[3], accB[3];
    accA[0] = accA[1] = accA[2] = pack2(0.f, 0.f);
    accB[0] = accB[1] = accB[2] = pack2(0.f, 0.f);

    constexpr int XOJ = XO * ACOLS;
    constexpr int HJ  = PS * HACOLS;

    // one stage-1 conv from preloaded odd words o[3][4] (shared by pair)
    auto s1_one = [&](int l, const u64 (&o)[3][4], u64* wA, u64* wB) {
        const float* w1l = &swb.w[0][l][0][0];
        u64 aA[3] = {swb.b[l][0], swb.b[l][1], swb.b[l][2]};
        u64 aB[3] = {aA[0], aA[1], aA[2]};
#pragma unroll
        for (int j = 0; j < 3; j++) {
            alignas(16) float wf[16];
            ((float4*)wf)[0] = ((const float4*)(w1l + j * 16))[0];
            ((float4*)wf)[1] = ((const float4*)(w1l + j * 16))[1];
            ((float4*)wf)[2] = ((const float4*)(w1l + j * 16))[2];
            ((float4*)wf)[3] = ((const float4*)(w1l + j * 16))[3];
            if (j == 0) { conv_j<0>(wf, aA, o[0][0], o[0][1], o[0][2], Mh[0][0], Mh[0][1]); conv_j<0>(wf, aB, o[0][1], o[0][2], o[0][3], Mh[0][1], Mh[0][2]); }
            if (j == 1) { conv_j<1>(wf, aA, o[1][0], o[1][1], o[1][2], Mh[1][0], Mh[1][1]); conv_j<1>(wf, aB, o[1][1], o[1][2], o[1][3], Mh[1][1], Mh[1][2]); }
            if (j == 2) { conv_j<2>(wf, aA, o[2][0], o[2][1], o[2][2], Mh[2][0], Mh[2][1]); conv_j<2>(wf, aB, o[2][1], o[2][2], o[2][3], Mh[2][1], Mh[2][2]); }
        }
#pragma unroll
        for (int i = 0; i < 3; i++) {
            float lo, hi;
            unpack2(aA[i], lo, hi);
            lo = (cokA && rlo) ? elu_f(lo) : 0.f;
            hi = (cokA && rhi) ? elu_f(hi) : 0.f;
            wA[i * HJ] = pack2(lo, hi);
            unpack2(aB[i], lo, hi);
            lo = (cokB && rlo) ? elu_f(lo) : 0.f;
            hi = (cokB && rhi) ? elu_f(hi) : 0.f;
            wB[i * HJ] = pack2(lo, hi);
        }
    };

    // stage-1 latent pair: load odd x words once, run two convs
    auto do_s1_pair = [&](int l0, u64* wA0, u64* wB0, u64* wA1, u64* wB1) {
        if (!sact) return;
        u64 o[3][4];
#pragma unroll
        for (int j = 0; j < 3; j++) {
            o[j][0] = xoA0[j * XOJ];
            o[j][1] = xoB0[j * XOJ];
            o[j][2] = xoA0[j * XOJ + 1];
            o[j][3] = xoB0[j * XOJ + 1];
        }
        s1_one(l0, o, wA0, wB0);
        s1_one(l0 + 1, o, wA1, wB1);
    };

    auto do_s2 = [&](int l, const u64* rdA, const u64* rdB) {
        const float* w2l = &swb.w[1][l][0][0];
#pragma unroll
        for (int j = 0; j < 3; j++) {
            const u64* pa = rdA + j * HJ;
            const u64* pb = rdB + j * HJ;
            u64 a0 = pa[0], b0 = pb[0], a1 = pa[1], b1 = pb[1];
            u64 A0 = pa[HACOLS], B0 = pb[HACOLS], A1 = pa[HACOLS + 1], B1 = pb[HACOLS + 1];
            u64 o0 = cmb(a0, A0), o1 = cmb(b0, B0), o2 = cmb(a1, A1), o3 = cmb(b1, B1);
            alignas(16) float wf[16];
            ((float4*)wf)[0] = ((const float4*)(w2l + j * 16))[0];
            ((float4*)wf)[1] = ((const float4*)(w2l + j * 16))[1];
            ((float4*)wf)[2] = ((const float4*)(w2l + j * 16))[2];
            ((float4*)wf)[3] = ((const float4*)(w2l + j * 16))[3];
            if (j == 0) { conv_j<0>(wf, accA, o0, o1, o2, A0, B0); conv_j<0>(wf, accB, o1, o2, o3, B0, A1); }
            if (j == 1) { conv_j<1>(wf, accA, o0, o1, o2, A0, B0); conv_j<1>(wf, accB, o1, o2, o3, B0, A1); }
            if (j == 2) { conv_j<2>(wf, accA, o0, o1, o2, A0, B0); conv_j<2>(wf, accB, o1, o2, o3, B0, A1); }
        }
    };

    // ---- depth-2 pipelined latent loop (8 barriers total) ----
    do_s1_pair(0, hwA[0], hwB[0], hwA[1], hwB[1]);
    __syncthreads();
#pragma unroll 1
    for (int l = 0; l < L_DIM; l += 4) {
        do_s1_pair(l + 2, hwA[2], hwB[2], hwA[3], hwB[3]);
        if (s2act) { do_s2(l, rA[0], rB[0]); do_s2(l + 1, rA[1], rB[1]); }
        __syncthreads();
        if (l + 4 < L_DIM) do_s1_pair(l + 4, hwA[0], hwB[0], hwA[1], hwB[1]);
        if (s2act) { do_s2(l + 2, rA[2], rB[2]); do_s2(l + 3, rA[3], rB[3]); }
        __syncthreads();
    }

    // ---- epilogue: mean + gated residual (tid < 128) ----
    if (s2act) {
        const float r = res[0];
        const float g = (r > 0.f) ? r : 0.f;
        const int gy = gy0 + 2 * tpy;
        const int gxA = gx0 + 2 * tcx;
        float* ob = out + (size_t)b * 3 * 128 * 128;
#pragma unroll
        for (int i = 0; i < 3; i++) {
            float lo, hi, xlo, xhi;
            unpack2(accA[i], lo, hi);
            unpack2(xsE[i][tpy + 2][2 * tcx + 2], xlo, xhi);
            ob[(i * 128 + gy) * 128 + gxA]     = lo * (1.f / 16.f) + g * xlo;
            ob[(i * 128 + gy + 1) * 128 + gxA] = hi * (1.f / 16.f) + g * xhi;
            unpack2(accB[i], lo, hi);
            unpack2(xsE[i][tpy + 2][2 * tcx + 3], xlo, xhi);
            ob[(i * 128 + gy) * 128 + gxA + 1]     = lo * (1.f / 16.f) + g * xlo;
            ob[(i * 128 + gy + 1) * 128 + gxA + 1] = hi * (1.f / 16.f) + g * xhi;
        }
    }
}

extern "C" void kernel_launch(void* const* d_in, const int* in_sizes, int n_in,
                              void* d_out, int out_size) {
    const float* x  = (const float*)d_in[0];
    const float* w1 = (const float*)d_in[1];
    const float* c1 = (const float*)d_in[2];
    const float* b1 = (const float*)d_in[3];
    const float* w2 = (const float*)d_in[4];
    const float* c2 = (const float*)d_in[5];
    const float* rs = (const float*)d_in[6];
    (void)in_sizes; (void)n_in; (void)out_size;

    prep_kernel<<<1, 32>>>(w1, c1, b1, w2, c2);

    dim3 grid(128 / TX, 128 / TY, 64);
    fused_kernel<<<grid, NT>>>(x, rs, (float*)d_out);
}